// round 12
// baseline (speedup 1.0000x reference)
#include <cuda_runtime.h>

#define N_NODES 100000
#define N_PAD   102400            // 25 tiles * 4096 (int4 scan, no bounds checks)
#define N_EDGES 3200000
#define IN_DIM  128
#define HID     16

// Scratch (device globals, ~26.2 MB). CRITICAL RULE (root cause of rounds
// 6-9 failures): NEVER pass a __device__ symbol as a kernel argument from
// host code — the host-side shadow address gets passed, the kernel derefs a
// host VA, and HMM backs it with a 128 MiB device arena, tripping the
// harness mem-guard. All globals are referenced directly in device code.
__device__ __align__(16) float g_bufA[N_NODES * HID];  // hs1 = (x@W1)*dinv (6.4 MB)
__device__ __align__(16) float g_bufB[N_NODES * HID];  // hs2 = (act@W2)*dinv (6.4 MB)
__device__ int g_srcs[N_EDGES];                        // dst-sorted src ids (12.8 MB)
__device__ __align__(16) int g_cursor[N_PAD];          // hist -> excl -> incl prefix
__device__ int g_is64;

// ---------------------------------------------------------------------------
// K0: zero cursor (incl. padding); thread 0 also detects edge_index dtype
// (int64 ids < 2^31 -> all odd 32-bit words zero).
__global__ void k_zero(const unsigned int* __restrict__ ei32) {
    int i = blockIdx.x * blockDim.x + threadIdx.x;
    if (i < N_PAD) g_cursor[i] = 0;
    if (i == 0) {
        int is64 = 1;
        #pragma unroll
        for (int k = 0; k < 64; k++)
            if (ei32[2 * k + 1] != 0u) { is64 = 0; break; }
        g_is64 = is64;
    }
}

// K1: in-degree histogram over dst (into g_cursor)
__global__ void k_hist(const void* __restrict__ ei) {
    int e = blockIdx.x * blockDim.x + threadIdx.x;
    if (e < N_EDGES) {
        int d;
        if (g_is64) d = (int)((const long long*)ei)[N_EDGES + e];
        else        d = ((const int*)ei)[N_EDGES + e];
        atomicAdd(&g_cursor[d], 1);
    }
}

// K2: single-block exclusive scan of g_cursor IN PLACE (replaces 3 kernels).
// 1024 threads, 25 tiles of 4096 (int4 per thread), warp shfl-scan +
// cross-warp scan + running carry in shared.
__global__ void k_scan() {
    __shared__ int sh_warp[32];
    __shared__ int sh_carry;
    const int t    = threadIdx.x;
    const int wid  = t >> 5;
    const int lane = t & 31;
    if (t == 0) sh_carry = 0;
    __syncthreads();

    int4* cur4 = reinterpret_cast<int4*>(g_cursor);
    #pragma unroll 1
    for (int tile = 0; tile < N_PAD / 4096; tile++) {
        const int idx = tile * 1024 + t;
        int4 v = cur4[idx];
        const int sum4 = v.x + v.y + v.z + v.w;

        // inclusive warp scan of per-thread sums
        int s = sum4;
        #pragma unroll
        for (int o = 1; o < 32; o <<= 1) {
            int a = __shfl_up_sync(0xffffffffu, s, o);
            if (lane >= o) s += a;
        }
        if (lane == 31) sh_warp[wid] = s;
        __syncthreads();
        if (t < 32) {
            int w = sh_warp[t];
            #pragma unroll
            for (int o = 1; o < 32; o <<= 1) {
                int a = __shfl_up_sync(0xffffffffu, w, o);
                if (t >= o) w += a;
            }
            sh_warp[t] = w;
        }
        __syncthreads();

        const int carry   = sh_carry;
        const int warpoff = (wid > 0) ? sh_warp[wid - 1] : 0;
        const int inc     = s + warpoff + carry;   // inclusive through this int4
        const int e       = inc - sum4;            // exclusive base
        int4 o4;
        o4.x = e;
        o4.y = e + v.x;
        o4.z = e + v.x + v.y;
        o4.w = e + v.x + v.y + v.z;
        cur4[idx] = o4;
        __syncthreads();                           // all read sh_carry first
        if (t == 1023) sh_carry = inc;             // tile total carried forward
        __syncthreads();
    }
}

// K3: permute src ids into dst-sorted order. Cursors advance from exclusive
// prefix (start) to inclusive prefix (end); cnt reconstructed from diffs.
__global__ void k_permute(const void* __restrict__ ei) {
    int e = blockIdx.x * blockDim.x + threadIdx.x;
    if (e >= N_EDGES) return;
    int s, d;
    if (g_is64) {
        const long long* p = (const long long*)ei;
        s = (int)p[e]; d = (int)p[N_EDGES + e];
    } else {
        const int* p = (const int*)ei;
        s = p[e]; d = p[N_EDGES + e];
    }
    int pos = atomicAdd(&g_cursor[d], 1);
    g_srcs[pos] = s;
}

// dinv = rsqrt(deg+1) from inclusive-prefix cursor (+1 = self loop)
__device__ __forceinline__ float dinv_of(int i) {
    int end   = g_cursor[i];
    int start = (i == 0) ? 0 : g_cursor[i - 1];
    return rsqrtf((float)(end - start) + 1.0f);
}

// K4: hs1 = (x @ W1) * dinv[node] -> g_bufA. 16 rows/block, 256 threads.
__global__ void k_gemm1(const float* __restrict__ x, const float* __restrict__ W1) {
    __shared__ float xs[16][IN_DIM];
    __shared__ float ws[IN_DIM][HID];
    const int t = threadIdx.x;
    const int row0 = blockIdx.x * 16;

    #pragma unroll
    for (int i = t; i < IN_DIM * HID; i += 256)
        ws[i >> 4][i & 15] = W1[i];
    #pragma unroll
    for (int i = t; i < 16 * IN_DIM; i += 256)
        xs[i >> 7][i & 127] = x[row0 * IN_DIM + i];
    __syncthreads();

    const int r = t >> 4, c = t & 15;
    float s = 0.0f;
    #pragma unroll
    for (int k = 0; k < IN_DIM; k++)
        s = fmaf(xs[r][k], ws[k][c], s);

    const int node = row0 + r;
    g_bufA[node * HID + c] = s * dinv_of(node);
}

// ---------------------------------------------------------------------------
// Shared gather+reduce core: warp per node, no atomics, no per-edge norms.
// Returns acc (all lanes hold the full sum for quad q = lane&3).
__device__ __forceinline__ float4 warp_gather(const float* __restrict__ h,
                                              int start, int cnt, int lane, int q) {
    float4 acc = make_float4(0.f, 0.f, 0.f, 0.f);
    for (int base = 0; base < cnt; base += 32) {
        const int m = cnt - base;             // valid edges in this chunk
        int src_l = 0;                        // inert fill: weight 0
        float w_l = 0.0f;
        if (lane < m) { src_l = g_srcs[start + base + lane]; w_l = 1.0f; }
        #pragma unroll
        for (int r = 0; r < 4; r++) {
            if (8 * r >= m) break;            // uniform per warp
            const int j = (lane >> 2) + 8 * r;
            const int   src = __shfl_sync(0xffffffffu, src_l, j);
            const float w   = __shfl_sync(0xffffffffu, w_l,   j);
            float4 v = reinterpret_cast<const float4*>(h)[src * 4 + q];
            acc.x = fmaf(v.x, w, acc.x);
            acc.y = fmaf(v.y, w, acc.y);
            acc.z = fmaf(v.z, w, acc.z);
            acc.w = fmaf(v.w, w, acc.w);
        }
    }
    #pragma unroll
    for (int ofs = 4; ofs < 32; ofs <<= 1) {
        acc.x += __shfl_xor_sync(0xffffffffu, acc.x, ofs);
        acc.y += __shfl_xor_sync(0xffffffffu, acc.y, ofs);
        acc.z += __shfl_xor_sync(0xffffffffu, acc.z, ofs);
        acc.w += __shfl_xor_sync(0xffffffffu, acc.w, ofs);
    }
    return acc;
}

// K5: layer-1 aggregation FUSED with gemm2.
// act(q) = relu(dinv*(acc+hs1[node]) + b1); h2 = act @ W2 (in-warp, W2 in
// shared); hs2 = h2 * dinv -> g_bufB. Reads bufA, writes bufB (no hazard).
__global__ void k_agg1(const float* __restrict__ b1, const float* __restrict__ W2) {
    __shared__ float ws[HID][HID];
    {
        const int t = threadIdx.x;   // 256 threads == 16*16
        ws[t >> 4][t & 15] = W2[t];
    }
    __syncthreads();

    const int warp = (blockIdx.x * blockDim.x + threadIdx.x) >> 5;
    if (warp >= N_NODES) return;
    const int lane = threadIdx.x & 31;
    const int node = warp;
    const int end   = g_cursor[node];
    const int start = (node == 0) ? 0 : g_cursor[node - 1];
    const int cnt   = end - start;
    const int q     = lane & 3;
    const float dnode = rsqrtf((float)cnt + 1.0f);

    float4 acc = warp_gather(g_bufA, start, cnt, lane, q);

    // act quad for q in EVERY lane (same-q lanes broadcast-load same addr)
    float4 self = reinterpret_cast<const float4*>(g_bufA)[node * 4 + q];
    float4 bv   = reinterpret_cast<const float4*>(b1)[q];
    float4 a;
    a.x = fmaxf(fmaf(acc.x + self.x, dnode, bv.x), 0.f);
    a.y = fmaxf(fmaf(acc.y + self.y, dnode, bv.y), 0.f);
    a.z = fmaxf(fmaf(acc.z + self.z, dnode, bv.z), 0.f);
    a.w = fmaxf(fmaf(acc.w + self.w, dnode, bv.w), 0.f);

    // in-warp gemm2: lane c (0..15) computes h2[c] = sum_k act[k]*W2[k][c]
    float s = 0.0f;
    #pragma unroll
    for (int qq = 0; qq < 4; qq++) {
        const float ax = __shfl_sync(0xffffffffu, a.x, qq);
        const float ay = __shfl_sync(0xffffffffu, a.y, qq);
        const float az = __shfl_sync(0xffffffffu, a.z, qq);
        const float aw = __shfl_sync(0xffffffffu, a.w, qq);
        const int c = lane & 15;
        s = fmaf(ax, ws[4 * qq + 0][c], s);
        s = fmaf(ay, ws[4 * qq + 1][c], s);
        s = fmaf(az, ws[4 * qq + 2][c], s);
        s = fmaf(aw, ws[4 * qq + 3][c], s);
    }
    if (lane < 16)
        g_bufB[node * HID + lane] = s * dnode;
}

// K6: layer-2 aggregation -> final output (reads bufB).
// out[node] = b2 + dinv*(acc + hs2[node])
__global__ void k_agg2(const float* __restrict__ b2, float* __restrict__ out) {
    const int warp = (blockIdx.x * blockDim.x + threadIdx.x) >> 5;
    if (warp >= N_NODES) return;
    const int lane = threadIdx.x & 31;
    const int node = warp;
    const int end   = g_cursor[node];
    const int start = (node == 0) ? 0 : g_cursor[node - 1];
    const int cnt   = end - start;
    const int q     = lane & 3;
    const float dnode = rsqrtf((float)cnt + 1.0f);

    float4 acc = warp_gather(g_bufB, start, cnt, lane, q);

    if (lane < 4) {
        float4 self = reinterpret_cast<const float4*>(g_bufB)[node * 4 + q];
        float4 bv   = reinterpret_cast<const float4*>(b2)[q];
        float4 o;
        o.x = fmaf(acc.x + self.x, dnode, bv.x);
        o.y = fmaf(acc.y + self.y, dnode, bv.y);
        o.z = fmaf(acc.z + self.z, dnode, bv.z);
        o.w = fmaf(acc.w + self.w, dnode, bv.w);
        reinterpret_cast<float4*>(out)[node * 4 + q] = o;
    }
}

extern "C" void kernel_launch(void* const* d_in, const int* in_sizes, int n_in,
                              void* d_out, int out_size) {
    const float* x   = (const float*)d_in[0];
    const void*  ei  = d_in[1];                 // [2,E] int64 OR int32 (detected)
    const float* W1  = (const float*)d_in[2];
    const float* b1  = (const float*)d_in[3];
    const float* W2  = (const float*)d_in[4];
    const float* b2  = (const float*)d_in[5];
    float*       out = (float*)d_out;

    const int padBlocks  = (N_PAD + 255) / 256;            // 400
    const int edgeBlocks = (N_EDGES + 255) / 256;          // 12500
    const int rowBlocks  = N_NODES / 16;                   // 6250
    const int aggBlocks  = (N_NODES * 32 + 255) / 256;     // 12500

    k_zero   <<<padBlocks, 256>>>((const unsigned int*)ei);
    k_hist   <<<edgeBlocks, 256>>>(ei);
    k_scan   <<<1, 1024>>>();
    k_permute<<<edgeBlocks, 256>>>(ei);
    k_gemm1  <<<rowBlocks, 256>>>(x, W1);
    k_agg1   <<<aggBlocks, 256>>>(b1, W2);      // act + gemm2 fused -> g_bufB
    k_agg2   <<<aggBlocks, 256>>>(b2, out);     // final -> d_out
}

// round 13
// speedup vs baseline: 1.0883x; 1.0883x over previous
#include <cuda_runtime.h>

#define N_NODES 100000
#define N_EDGES 3200000
#define IN_DIM  128
#define HID     16
#define SB1     512
#define SCAN_BLOCKS ((N_NODES + SB1 - 1) / SB1)   // 196

// Scratch (device globals, ~26 MB). CRITICAL RULE (root cause of rounds 6-9
// failures): NEVER pass a __device__ symbol as a kernel argument from host
// code — the host-side shadow address gets passed, the kernel derefs a host
// VA, and HMM backs it with a 128 MiB device arena, tripping the harness
// mem-guard. All globals are referenced directly in device code.
__device__ __align__(16) float g_bufA[N_NODES * HID];  // hs1 = (x@W1)*dinv (6.4 MB)
__device__ __align__(16) float g_bufB[N_NODES * HID];  // hs2 = (act@W2)*dinv (6.4 MB)
__device__ int g_srcs  [N_EDGES];                      // dst-sorted src ids (12.8 MB)
__device__ int g_cursor[N_NODES];                      // hist -> excl -> incl prefix
__device__ int g_bsum [SCAN_BLOCKS];
__device__ int g_bbase[256];
__device__ int g_is64;

// ---------------------------------------------------------------------------
// K0: zero cursor; thread 0 also detects edge_index dtype
// (int64 ids < 2^31 -> all odd 32-bit words zero).
__global__ void k_zero(const unsigned int* __restrict__ ei32) {
    int i = blockIdx.x * blockDim.x + threadIdx.x;
    if (i < N_NODES) g_cursor[i] = 0;
    if (i == 0) {
        int is64 = 1;
        #pragma unroll
        for (int k = 0; k < 64; k++)
            if (ei32[2 * k + 1] != 0u) { is64 = 0; break; }
        g_is64 = is64;
    }
}

// K1: in-degree histogram over dst (into g_cursor)
__global__ void k_hist(const void* __restrict__ ei) {
    int e = blockIdx.x * blockDim.x + threadIdx.x;
    if (e < N_EDGES) {
        int d;
        if (g_is64) d = (int)((const long long*)ei)[N_EDGES + e];
        else        d = ((const int*)ei)[N_EDGES + e];
        atomicAdd(&g_cursor[d], 1);
    }
}

// K2a: per-block exclusive scan of g_cursor IN PLACE; block sums -> g_bsum
// (parallel 3-kernel scan: the single-block fused scan cost +45 us in R12)
__global__ void k_scan1() {
    __shared__ int sh[SB1];
    const int t = threadIdx.x;
    const int i = blockIdx.x * SB1 + t;
    int v = (i < N_NODES) ? g_cursor[i] : 0;
    sh[t] = v;
    __syncthreads();
    #pragma unroll
    for (int o = 1; o < SB1; o <<= 1) {
        int a = (t >= o) ? sh[t - o] : 0;
        __syncthreads();
        sh[t] += a;
        __syncthreads();
    }
    if (i < N_NODES) g_cursor[i] = sh[t] - v;            // local exclusive
    if (t == SB1 - 1) g_bsum[blockIdx.x] = sh[SB1 - 1];  // block total
}

// K2b: scan the block sums (single block, 256 >= 196)
__global__ void k_scan2() {
    __shared__ int sh[256];
    const int t = threadIdx.x;
    int v = (t < SCAN_BLOCKS) ? g_bsum[t] : 0;
    sh[t] = v;
    __syncthreads();
    #pragma unroll
    for (int o = 1; o < 256; o <<= 1) {
        int a = (t >= o) ? sh[t - o] : 0;
        __syncthreads();
        sh[t] += a;
        __syncthreads();
    }
    g_bbase[t] = sh[t] - v;
}

// K2c: add block bases -> global exclusive prefix (= segment starts)
__global__ void k_scan3() {
    int i = blockIdx.x * blockDim.x + threadIdx.x;
    if (i < N_NODES) g_cursor[i] += g_bbase[i / SB1];
}

// K3: permute src ids into dst-sorted order. Cursors advance from exclusive
// prefix (start) to inclusive prefix (end); cnt reconstructed from diffs.
__global__ void k_permute(const void* __restrict__ ei) {
    int e = blockIdx.x * blockDim.x + threadIdx.x;
    if (e >= N_EDGES) return;
    int s, d;
    if (g_is64) {
        const long long* p = (const long long*)ei;
        s = (int)p[e]; d = (int)p[N_EDGES + e];
    } else {
        const int* p = (const int*)ei;
        s = p[e]; d = p[N_EDGES + e];
    }
    int pos = atomicAdd(&g_cursor[d], 1);
    g_srcs[pos] = s;
}

// dinv = rsqrt(deg+1) from inclusive-prefix cursor (+1 = self loop)
__device__ __forceinline__ float dinv_of(int i) {
    int end   = g_cursor[i];
    int start = (i == 0) ? 0 : g_cursor[i - 1];
    return rsqrtf((float)(end - start) + 1.0f);
}

// K4: hs1 = (x @ W1) * dinv[node] -> g_bufA. 16 rows/block, 256 threads.
__global__ void k_gemm1(const float* __restrict__ x, const float* __restrict__ W1) {
    __shared__ float xs[16][IN_DIM];
    __shared__ float ws[IN_DIM][HID];
    const int t = threadIdx.x;
    const int row0 = blockIdx.x * 16;

    #pragma unroll
    for (int i = t; i < IN_DIM * HID; i += 256)
        ws[i >> 4][i & 15] = W1[i];
    #pragma unroll
    for (int i = t; i < 16 * IN_DIM; i += 256)
        xs[i >> 7][i & 127] = x[row0 * IN_DIM + i];
    __syncthreads();

    const int r = t >> 4, c = t & 15;
    float s = 0.0f;
    #pragma unroll
    for (int k = 0; k < IN_DIM; k++)
        s = fmaf(xs[r][k], ws[k][c], s);

    const int node = row0 + r;
    g_bufA[node * HID + c] = s * dinv_of(node);
}

// ---------------------------------------------------------------------------
// Shared gather+reduce core: warp per node, no atomics, no per-edge norms.
// Returns acc (all lanes hold the full sum for quad q = lane&3).
__device__ __forceinline__ float4 warp_gather(const float* __restrict__ h,
                                              int start, int cnt, int lane, int q) {
    float4 acc = make_float4(0.f, 0.f, 0.f, 0.f);
    for (int base = 0; base < cnt; base += 32) {
        const int m = cnt - base;             // valid edges in this chunk
        int src_l = 0;                        // inert fill: weight 0
        float w_l = 0.0f;
        if (lane < m) { src_l = g_srcs[start + base + lane]; w_l = 1.0f; }
        #pragma unroll
        for (int r = 0; r < 4; r++) {
            if (8 * r >= m) break;            // uniform per warp
            const int j = (lane >> 2) + 8 * r;
            const int   src = __shfl_sync(0xffffffffu, src_l, j);
            const float w   = __shfl_sync(0xffffffffu, w_l,   j);
            float4 v = reinterpret_cast<const float4*>(h)[src * 4 + q];
            acc.x = fmaf(v.x, w, acc.x);
            acc.y = fmaf(v.y, w, acc.y);
            acc.z = fmaf(v.z, w, acc.z);
            acc.w = fmaf(v.w, w, acc.w);
        }
    }
    #pragma unroll
    for (int ofs = 4; ofs < 32; ofs <<= 1) {
        acc.x += __shfl_xor_sync(0xffffffffu, acc.x, ofs);
        acc.y += __shfl_xor_sync(0xffffffffu, acc.y, ofs);
        acc.z += __shfl_xor_sync(0xffffffffu, acc.z, ofs);
        acc.w += __shfl_xor_sync(0xffffffffu, acc.w, ofs);
    }
    return acc;
}

// K5: layer-1 aggregation FUSED with gemm2.
// act(q) = relu(dinv*(acc+hs1[node]) + b1); h2 = act @ W2 (in-warp, W2 in
// shared); hs2 = h2 * dinv -> g_bufB. Reads bufA, writes bufB (no hazard).
__global__ void k_agg1(const float* __restrict__ b1, const float* __restrict__ W2) {
    __shared__ float ws[HID][HID];
    {
        const int t = threadIdx.x;   // 256 threads == 16*16
        ws[t >> 4][t & 15] = W2[t];
    }
    __syncthreads();

    const int warp = (blockIdx.x * blockDim.x + threadIdx.x) >> 5;
    if (warp >= N_NODES) return;
    const int lane = threadIdx.x & 31;
    const int node = warp;
    const int end   = g_cursor[node];
    const int start = (node == 0) ? 0 : g_cursor[node - 1];
    const int cnt   = end - start;
    const int q     = lane & 3;
    const float dnode = rsqrtf((float)cnt + 1.0f);

    float4 acc = warp_gather(g_bufA, start, cnt, lane, q);

    // act quad for q in EVERY lane (same-q lanes broadcast-load same addr)
    float4 self = reinterpret_cast<const float4*>(g_bufA)[node * 4 + q];
    float4 bv   = reinterpret_cast<const float4*>(b1)[q];
    float4 a;
    a.x = fmaxf(fmaf(acc.x + self.x, dnode, bv.x), 0.f);
    a.y = fmaxf(fmaf(acc.y + self.y, dnode, bv.y), 0.f);
    a.z = fmaxf(fmaf(acc.z + self.z, dnode, bv.z), 0.f);
    a.w = fmaxf(fmaf(acc.w + self.w, dnode, bv.w), 0.f);

    // in-warp gemm2: lane c (0..15) computes h2[c] = sum_k act[k]*W2[k][c]
    float s = 0.0f;
    #pragma unroll
    for (int qq = 0; qq < 4; qq++) {
        const float ax = __shfl_sync(0xffffffffu, a.x, qq);
        const float ay = __shfl_sync(0xffffffffu, a.y, qq);
        const float az = __shfl_sync(0xffffffffu, a.z, qq);
        const float aw = __shfl_sync(0xffffffffu, a.w, qq);
        const int c = lane & 15;
        s = fmaf(ax, ws[4 * qq + 0][c], s);
        s = fmaf(ay, ws[4 * qq + 1][c], s);
        s = fmaf(az, ws[4 * qq + 2][c], s);
        s = fmaf(aw, ws[4 * qq + 3][c], s);
    }
    if (lane < 16)
        g_bufB[node * HID + lane] = s * dnode;
}

// K6: layer-2 aggregation -> final output (reads bufB).
// out[node] = b2 + dinv*(acc + hs2[node])
__global__ void k_agg2(const float* __restrict__ b2, float* __restrict__ out) {
    const int warp = (blockIdx.x * blockDim.x + threadIdx.x) >> 5;
    if (warp >= N_NODES) return;
    const int lane = threadIdx.x & 31;
    const int node = warp;
    const int end   = g_cursor[node];
    const int start = (node == 0) ? 0 : g_cursor[node - 1];
    const int cnt   = end - start;
    const int q     = lane & 3;
    const float dnode = rsqrtf((float)cnt + 1.0f);

    float4 acc = warp_gather(g_bufB, start, cnt, lane, q);

    if (lane < 4) {
        float4 self = reinterpret_cast<const float4*>(g_bufB)[node * 4 + q];
        float4 bv   = reinterpret_cast<const float4*>(b2)[q];
        float4 o;
        o.x = fmaf(acc.x + self.x, dnode, bv.x);
        o.y = fmaf(acc.y + self.y, dnode, bv.y);
        o.z = fmaf(acc.z + self.z, dnode, bv.z);
        o.w = fmaf(acc.w + self.w, dnode, bv.w);
        reinterpret_cast<float4*>(out)[node * 4 + q] = o;
    }
}

extern "C" void kernel_launch(void* const* d_in, const int* in_sizes, int n_in,
                              void* d_out, int out_size) {
    const float* x   = (const float*)d_in[0];
    const void*  ei  = d_in[1];                 // [2,E] int64 OR int32 (detected)
    const float* W1  = (const float*)d_in[2];
    const float* b1  = (const float*)d_in[3];
    const float* W2  = (const float*)d_in[4];
    const float* b2  = (const float*)d_in[5];
    float*       out = (float*)d_out;

    const int nodeBlocks = (N_NODES + 255) / 256;          // 391
    const int edgeBlocks = (N_EDGES + 255) / 256;          // 12500
    const int rowBlocks  = N_NODES / 16;                   // 6250
    const int aggBlocks  = (N_NODES * 32 + 255) / 256;     // 12500

    k_zero   <<<nodeBlocks, 256>>>((const unsigned int*)ei);
    k_hist   <<<edgeBlocks, 256>>>(ei);
    k_scan1  <<<SCAN_BLOCKS, SB1>>>();
    k_scan2  <<<1, 256>>>();
    k_scan3  <<<nodeBlocks, 256>>>();
    k_permute<<<edgeBlocks, 256>>>(ei);
    k_gemm1  <<<rowBlocks, 256>>>(x, W1);
    k_agg1   <<<aggBlocks, 256>>>(b1, W2);      // act + gemm2 fused -> g_bufB
    k_agg2   <<<aggBlocks, 256>>>(b2, out);     // final -> d_out
}

// round 14
// speedup vs baseline: 1.1948x; 1.0978x over previous
#include <cuda_runtime.h>

#define N_NODES 100000
#define N_EDGES 3200000
#define IN_DIM  128
#define HID     16
#define SB1     512
#define SCAN_BLOCKS ((N_NODES + SB1 - 1) / SB1)   // 196

// Scratch (device globals, ~20 MB). CRITICAL RULE (root cause of rounds 6-9
// failures): NEVER pass a __device__ symbol as a kernel argument from host
// code — the host-side shadow address gets passed, the kernel derefs a host
// VA, and HMM backs it with a 128 MiB device arena, tripping the harness
// mem-guard. All globals are referenced directly in device code.
__device__ __align__(16) float g_buf[N_NODES * HID];   // hs1, then hs2 (6.4 MB)
__device__ int g_srcs  [N_EDGES];                      // dst-sorted src ids (12.8 MB)
__device__ int g_cnt   [N_NODES];                      // in-degree (kept!)
__device__ int g_cursor[N_NODES];                      // excl scan -> incl prefix
__device__ int g_bsum [SCAN_BLOCKS];
__device__ int g_bbase[256];
__device__ int g_is64;

// Fork-join stream/events, created at program load — BEFORE the harness's
// memory checkpoint and BEFORE graph capture starts. No device-memory APIs.
static cudaStream_t g_s2;
static cudaEvent_t  g_evFork, g_evJoin;
static struct _StreamInit {
    _StreamInit() {
        cudaStreamCreateWithFlags(&g_s2, cudaStreamNonBlocking);
        cudaEventCreateWithFlags(&g_evFork, cudaEventDisableTiming);
        cudaEventCreateWithFlags(&g_evJoin, cudaEventDisableTiming);
    }
} g_streamInit;

// ---------------------------------------------------------------------------
// K0: zero degree counts; thread 0 also detects edge_index dtype
// (int64 ids < 2^31 -> all odd 32-bit words zero).
__global__ void k_zero(const unsigned int* __restrict__ ei32) {
    int i = blockIdx.x * blockDim.x + threadIdx.x;
    if (i < N_NODES) g_cnt[i] = 0;
    if (i == 0) {
        int is64 = 1;
        #pragma unroll
        for (int k = 0; k < 64; k++)
            if (ei32[2 * k + 1] != 0u) { is64 = 0; break; }
        g_is64 = is64;
    }
}

// K1: in-degree histogram over dst (into g_cnt)
__global__ void k_hist(const void* __restrict__ ei) {
    int e = blockIdx.x * blockDim.x + threadIdx.x;
    if (e < N_EDGES) {
        int d;
        if (g_is64) d = (int)((const long long*)ei)[N_EDGES + e];
        else        d = ((const int*)ei)[N_EDGES + e];
        atomicAdd(&g_cnt[d], 1);
    }
}

// dinv = rsqrt(deg+1), straight from g_cnt (+1 = self loop).
// Depends ONLY on k_hist — this is what lets gemm1 overlap scan+permute.
__device__ __forceinline__ float dinv_of(int i) {
    return rsqrtf((float)g_cnt[i] + 1.0f);
}

// K2a: per-block exclusive scan: read g_cnt, write g_cursor; sums -> g_bsum
__global__ void k_scan1() {
    __shared__ int sh[SB1];
    const int t = threadIdx.x;
    const int i = blockIdx.x * SB1 + t;
    int v = (i < N_NODES) ? g_cnt[i] : 0;
    sh[t] = v;
    __syncthreads();
    #pragma unroll
    for (int o = 1; o < SB1; o <<= 1) {
        int a = (t >= o) ? sh[t - o] : 0;
        __syncthreads();
        sh[t] += a;
        __syncthreads();
    }
    if (i < N_NODES) g_cursor[i] = sh[t] - v;            // local exclusive
    if (t == SB1 - 1) g_bsum[blockIdx.x] = sh[SB1 - 1];  // block total
}

// K2b: scan the block sums (single block, 256 >= 196)
__global__ void k_scan2() {
    __shared__ int sh[256];
    const int t = threadIdx.x;
    int v = (t < SCAN_BLOCKS) ? g_bsum[t] : 0;
    sh[t] = v;
    __syncthreads();
    #pragma unroll
    for (int o = 1; o < 256; o <<= 1) {
        int a = (t >= o) ? sh[t - o] : 0;
        __syncthreads();
        sh[t] += a;
        __syncthreads();
    }
    g_bbase[t] = sh[t] - v;
}

// K2c: add block bases -> global exclusive prefix (= segment starts)
__global__ void k_scan3() {
    int i = blockIdx.x * blockDim.x + threadIdx.x;
    if (i < N_NODES) g_cursor[i] += g_bbase[i / SB1];
}

// K3: permute src ids into dst-sorted order. Cursors advance from exclusive
// prefix (start) to inclusive prefix (end); agg derives start = end - cnt.
__global__ void k_permute(const void* __restrict__ ei) {
    int e = blockIdx.x * blockDim.x + threadIdx.x;
    if (e >= N_EDGES) return;
    int s, d;
    if (g_is64) {
        const long long* p = (const long long*)ei;
        s = (int)p[e]; d = (int)p[N_EDGES + e];
    } else {
        const int* p = (const int*)ei;
        s = p[e]; d = p[N_EDGES + e];
    }
    int pos = atomicAdd(&g_cursor[d], 1);
    g_srcs[pos] = s;
}

// K4: hs1 = (x @ W1) * dinv[node] -> g_buf. 16 rows/block, 256 threads.
// Runs on the side stream, overlapped with scan+permute (needs only g_cnt).
__global__ void k_gemm1(const float* __restrict__ x, const float* __restrict__ W1) {
    __shared__ float xs[16][IN_DIM];
    __shared__ float ws[IN_DIM][HID];
    const int t = threadIdx.x;
    const int row0 = blockIdx.x * 16;

    #pragma unroll
    for (int i = t; i < IN_DIM * HID; i += 256)
        ws[i >> 4][i & 15] = W1[i];
    #pragma unroll
    for (int i = t; i < 16 * IN_DIM; i += 256)
        xs[i >> 7][i & 127] = x[row0 * IN_DIM + i];
    __syncthreads();

    const int r = t >> 4, c = t & 15;
    float s = 0.0f;
    #pragma unroll
    for (int k = 0; k < IN_DIM; k++)
        s = fmaf(xs[r][k], ws[k][c], s);

    const int node = row0 + r;
    g_buf[node * HID + c] = s * dinv_of(node);
}

// ---------------------------------------------------------------------------
// Shared gather+reduce core: warp per node, no atomics, no per-edge norms.
__device__ __forceinline__ float4 warp_gather(const float* __restrict__ h,
                                              int start, int cnt, int lane, int q) {
    float4 acc = make_float4(0.f, 0.f, 0.f, 0.f);
    for (int base = 0; base < cnt; base += 32) {
        const int m = cnt - base;             // valid edges in this chunk
        int src_l = 0;                        // inert fill: weight 0
        float w_l = 0.0f;
        if (lane < m) { src_l = g_srcs[start + base + lane]; w_l = 1.0f; }
        #pragma unroll
        for (int r = 0; r < 4; r++) {
            if (8 * r >= m) break;            // uniform per warp
            const int j = (lane >> 2) + 8 * r;
            const int   src = __shfl_sync(0xffffffffu, src_l, j);
            const float w   = __shfl_sync(0xffffffffu, w_l,   j);
            float4 v = reinterpret_cast<const float4*>(h)[src * 4 + q];
            acc.x = fmaf(v.x, w, acc.x);
            acc.y = fmaf(v.y, w, acc.y);
            acc.z = fmaf(v.z, w, acc.z);
            acc.w = fmaf(v.w, w, acc.w);
        }
    }
    #pragma unroll
    for (int ofs = 4; ofs < 32; ofs <<= 1) {
        acc.x += __shfl_xor_sync(0xffffffffu, acc.x, ofs);
        acc.y += __shfl_xor_sync(0xffffffffu, acc.y, ofs);
        acc.z += __shfl_xor_sync(0xffffffffu, acc.z, ofs);
        acc.w += __shfl_xor_sync(0xffffffffu, acc.w, ofs);
    }
    return acc;
}

// K5: aggregation (R11 structure — fusion reverted).
// dst[node] = (relu?)( bias + dinv[node] * ( hs[node] + sum_e hs[src_e] ) )
__global__ void k_agg(const float* __restrict__ bias,
                      float* __restrict__ dst,
                      int relu) {
    const int warp = (blockIdx.x * blockDim.x + threadIdx.x) >> 5;
    if (warp >= N_NODES) return;
    const float* __restrict__ h = g_buf;    // device symbol, device-side only
    const int lane = threadIdx.x & 31;
    const int node = warp;
    const int cnt   = g_cnt[node];
    const int start = g_cursor[node] - cnt; // cursor is inclusive after permute
    const int q     = lane & 3;
    const float dnode = rsqrtf((float)cnt + 1.0f);

    float4 acc = warp_gather(h, start, cnt, lane, q);

    if (lane < 4) {
        float4 self = reinterpret_cast<const float4*>(h)[node * 4 + q];
        float4 bv   = reinterpret_cast<const float4*>(bias)[q];
        float4 o;
        o.x = fmaf(acc.x + self.x, dnode, bv.x);
        o.y = fmaf(acc.y + self.y, dnode, bv.y);
        o.z = fmaf(acc.z + self.z, dnode, bv.z);
        o.w = fmaf(acc.w + self.w, dnode, bv.w);
        if (relu) {
            o.x = fmaxf(o.x, 0.f); o.y = fmaxf(o.y, 0.f);
            o.z = fmaxf(o.z, 0.f); o.w = fmaxf(o.w, 0.f);
        }
        reinterpret_cast<float4*>(dst)[node * 4 + q] = o;
    }
}

// K6: hs2 = (act @ W2) * dinv[node]. act lives in d_out (harness pointer);
// result overwrites g_buf (hs1 is dead).
__global__ void k_gemm2(const float* __restrict__ act, const float* __restrict__ W2) {
    __shared__ float hs[16][HID];
    __shared__ float ws[HID][HID];
    const int t = threadIdx.x;
    const int r = t >> 4, c = t & 15;
    ws[r][c] = W2[t];
    const int node = blockIdx.x * 16 + r;
    hs[r][c] = act[node * HID + c];
    __syncthreads();
    float s = 0.0f;
    #pragma unroll
    for (int k = 0; k < HID; k++)
        s = fmaf(hs[r][k], ws[k][c], s);
    g_buf[node * HID + c] = s * dinv_of(node);
}

extern "C" void kernel_launch(void* const* d_in, const int* in_sizes, int n_in,
                              void* d_out, int out_size) {
    const float* x   = (const float*)d_in[0];
    const void*  ei  = d_in[1];                 // [2,E] int64 OR int32 (detected)
    const float* W1  = (const float*)d_in[2];
    const float* b1  = (const float*)d_in[3];
    const float* W2  = (const float*)d_in[4];
    const float* b2  = (const float*)d_in[5];
    float*       out = (float*)d_out;

    const int nodeBlocks = (N_NODES + 255) / 256;          // 391
    const int edgeBlocks = (N_EDGES + 255) / 256;          // 12500
    const int rowBlocks  = N_NODES / 16;                   // 6250
    const int aggBlocks  = (N_NODES * 32 + 255) / 256;     // 12500

    k_zero   <<<nodeBlocks, 256>>>((const unsigned int*)ei);
    k_hist   <<<edgeBlocks, 256>>>(ei);

    // Fork: gemm1 (needs only g_cnt) overlaps scan+permute on side stream.
    cudaEventRecord(g_evFork, 0);
    cudaStreamWaitEvent(g_s2, g_evFork, 0);
    k_gemm1  <<<rowBlocks, 256, 0, g_s2>>>(x, W1);
    cudaEventRecord(g_evJoin, g_s2);

    k_scan1  <<<SCAN_BLOCKS, SB1>>>();
    k_scan2  <<<1, 256>>>();
    k_scan3  <<<nodeBlocks, 256>>>();
    k_permute<<<edgeBlocks, 256>>>(ei);

    // Join: agg1 needs both permute (main stream) and gemm1 (side stream).
    cudaStreamWaitEvent(0, g_evJoin, 0);

    k_agg    <<<aggBlocks, 256>>>(b1, out, 1);   // act -> d_out (scratch)
    k_gemm2  <<<rowBlocks, 256>>>(out, W2);      // hs2 -> g_buf
    k_agg    <<<aggBlocks, 256>>>(b2, out, 0);   // final -> d_out
}